// round 6
// baseline (speedup 1.0000x reference)
#include <cuda_runtime.h>
#include <cstdint>

// MoE gating via mma.sync tf32 (baseline PTX, runs on sm_103 tensor pipe).
// x:[16384,1024] f32, gate_w:[64,1024] f32.
// out (f32): top_scores [T,2] | top_idx [T,2] | total_loss [1].

#define H      1024
#define NE     64
#define TM     128
#define NT     256
#define KC     32
#define NCH    32
#define NBUF   4
#define AST    36                      // padded row stride (floats): conflict-free frags
#define ABYTES (TM * AST * 4)          // 18432
#define BBYTES (NE * AST * 4)          // 9216
#define BUFB   (ABYTES + BBYTES)       // 27648
#define DSMEM  (NBUF * BUFB)           // 110592
#define SP_STR 66                      // even: float2 stores aligned
#define NBLK   128
#define THETA  0.015f

__device__ float    g_pexp[NBLK * NE];
__device__ float    g_pz2[NBLK];
__device__ unsigned g_cnt = 0;

static __device__ __forceinline__ uint32_t su32(const void* p) {
    uint32_t a;
    asm("{ .reg .u64 t; cvta.to.shared.u64 t, %1; cvt.u32.u64 %0, t; }"
        : "=r"(a) : "l"(p));
    return a;
}

#define CMPGT(bx, ix, by, iy) (((bx) > (by)) || (((bx) == (by)) && ((ix) < (iy))))

static __device__ __forceinline__ void mma_tf32(float& c0, float& c1, float& c2, float& c3,
                                                uint32_t a0, uint32_t a1, uint32_t a2, uint32_t a3,
                                                uint32_t b0, uint32_t b1) {
    asm volatile(
        "mma.sync.aligned.m16n8k8.row.col.f32.tf32.tf32.f32 "
        "{%0,%1,%2,%3}, {%4,%5,%6,%7}, {%8,%9}, {%0,%1,%2,%3};"
        : "+f"(c0), "+f"(c1), "+f"(c2), "+f"(c3)
        : "r"(a0), "r"(a1), "r"(a2), "r"(a3), "r"(b0), "r"(b1));
}

static __device__ __forceinline__ void stage_chunk(const float* __restrict__ x,
                                                   const float* __restrict__ w,
                                                   int tBlk, int c,
                                                   uint32_t bufA, int tid) {
    // A: 128 rows x 8 quads of 16B
#pragma unroll
    for (int i = 0; i < 4; i++) {
        int idx = tid + NT * i;
        int row = idx >> 3, q = idx & 7;
        const float* g = x + (size_t)(tBlk + row) * H + c * KC + q * 4;
        uint32_t d = bufA + (row * AST + q * 4) * 4;
        asm volatile("cp.async.cg.shared.global [%0], [%1], 16;" :: "r"(d), "l"(g));
    }
    // B: 64 rows x 8 quads of 16B
#pragma unroll
    for (int i = 0; i < 2; i++) {
        int idx = tid + NT * i;
        int row = idx >> 3, q = idx & 7;
        const float* g = w + (size_t)row * H + c * KC + q * 4;
        uint32_t d = bufA + ABYTES + (row * AST + q * 4) * 4;
        asm volatile("cp.async.cg.shared.global [%0], [%1], 16;" :: "r"(d), "l"(g));
    }
}

__global__ __launch_bounds__(NT) void moe_gate(const float* __restrict__ x,
                                               const float* __restrict__ w,
                                               float* __restrict__ out,
                                               int T) {
    extern __shared__ __align__(16) char dsm[];
    __shared__ int      s_cnt2;
    __shared__ int      s_list[64];
    __shared__ float    s_part[4][NE];
    __shared__ float    s_red[8];
    __shared__ unsigned s_last;

    const int tid  = threadIdx.x;
    const int wid  = tid >> 5;
    const int lid  = tid & 31;
    const int lg   = lid >> 2;       // groupID
    const int lt   = lid & 3;        // threadID_in_group
    const int tBlk = blockIdx.x * TM;
    const uint32_t base = su32(dsm);

    if (tid == 0) s_cnt2 = 0;

    // warp tile: 32 tokens x 32 experts
    const int wr = wid & 3;          // token group
    const int wc = wid >> 2;         // expert group
    const int tb = wr * 32;
    const int eb = wc * 32;

    float C[2][4][4];
#pragma unroll
    for (int i = 0; i < 2; i++)
#pragma unroll
        for (int j = 0; j < 4; j++)
#pragma unroll
            for (int r = 0; r < 4; r++) C[i][j][r] = 0.0f;

    // ---- prologue ----
#pragma unroll
    for (int c = 0; c < NBUF; c++) {
        stage_chunk(x, w, tBlk, c, base + c * BUFB, tid);
        asm volatile("cp.async.commit_group;" ::: "memory");
    }

#pragma unroll 1
    for (int c = 0; c < NCH; c++) {
        asm volatile("cp.async.wait_group 3;" ::: "memory");
        __syncthreads();
        const float* As = (const float*)(dsm + (c & 3) * BUFB);
        const float* Bs = As + TM * AST;
#pragma unroll
        for (int kk = 0; kk < 4; kk++) {
            const int k0 = kk * 8;
            uint32_t a[2][4], b[4][2];
#pragma unroll
            for (int i = 0; i < 2; i++) {
                const float* ap = As + (tb + 16 * i + lg) * AST + k0 + lt;
                a[i][0] = __float_as_uint(ap[0]);
                a[i][1] = __float_as_uint(ap[8 * AST]);
                a[i][2] = __float_as_uint(ap[4]);
                a[i][3] = __float_as_uint(ap[8 * AST + 4]);
            }
#pragma unroll
            for (int j = 0; j < 4; j++) {
                const float* bp = Bs + (eb + 8 * j + lg) * AST + k0 + lt;
                b[j][0] = __float_as_uint(bp[0]);
                b[j][1] = __float_as_uint(bp[4]);
            }
#pragma unroll
            for (int i = 0; i < 2; i++)
#pragma unroll
                for (int j = 0; j < 4; j++)
                    mma_tf32(C[i][j][0], C[i][j][1], C[i][j][2], C[i][j][3],
                             a[i][0], a[i][1], a[i][2], a[i][3],
                             b[j][0], b[j][1]);
        }
        __syncthreads();
        if (c + NBUF < NCH)
            stage_chunk(x, w, tBlk, c + NBUF, base + (c & 3) * BUFB, tid);
        asm volatile("cp.async.commit_group;" ::: "memory");
    }

    // ---- logits -> smem [128][SP_STR] ----
    float* sP   = (float*)dsm;
    float* sInv = sP + TM * SP_STR;
#pragma unroll
    for (int i = 0; i < 2; i++)
#pragma unroll
        for (int j = 0; j < 4; j++) {
            int t = tb + 16 * i + lg;
            int e = eb + 8 * j + 2 * lt;
            *(float2*)(sP + t * SP_STR + e)       = make_float2(C[i][j][0], C[i][j][1]);
            *(float2*)(sP + (t + 8) * SP_STR + e) = make_float2(C[i][j][2], C[i][j][3]);
        }
    __syncthreads();

    // ---- per-token softmax / top-3 / flag ----
    float zsq = 0.0f;
    if (tid < TM) {
        float* row = sP + tid * SP_STR;
        float b1 = -1e30f, b2 = -1e30f, b3 = -1e30f;
        int   i1 = 0, i2 = 0;
#pragma unroll 8
        for (int e = 0; e < NE; e++) {
            float l = row[e];
            if (l > b1)      { b3 = b2; b2 = b1; i2 = i1; b1 = l; i1 = e; }
            else if (l > b2) { b3 = b2; b2 = l;  i2 = e; }
            else if (l > b3) { b3 = l; }
        }
        float m = b1, sum = 0.0f;
#pragma unroll 8
        for (int e = 0; e < NE; e++) {
            float ex = __expf(row[e] - m);
            sum += ex;
            row[e] = ex;
        }
        float inv = 1.0f / sum;
        sInv[tid] = inv;
        float z = m + __logf(sum);
        zsq = z * z;
        float p1 = __expf(b1 - m) * inv;
        float p2 = __expf(b2 - m) * inv;
        float dd = __expf(p2 - p1);
        int gt = tBlk + tid;
        out[2 * gt]             = 1.0f / (1.0f + dd);
        out[2 * gt + 1]         = dd / (1.0f + dd);
        out[2 * T + 2 * gt]     = (float)i1;
        out[2 * T + 2 * gt + 1] = (float)i2;
        if ((b1 - b2 < THETA) || (b2 - b3 < THETA)) {
            int pos = atomicAdd(&s_cnt2, 1);
            if (pos < 64) s_list[pos] = tid;
        }
    }

    // ---- loss partials ----
#pragma unroll
    for (int off = 16; off > 0; off >>= 1)
        zsq += __shfl_down_sync(0xffffffffu, zsq, off);
    if (lid == 0) s_red[wid] = zsq;
    __syncthreads();
    if (tid == 0) {
        float s = 0.0f;
#pragma unroll
        for (int i = 0; i < 8; i++) s += s_red[i];
        g_pz2[blockIdx.x] = s;
    }
    if (tid < NE) {
        float s = 0.0f;
#pragma unroll 4
        for (int t = 0; t < TM; t++) s += sP[t * SP_STR + tid] * sInv[t];
        g_pexp[blockIdx.x * NE + tid] = s;
    }

    // ---- rescue: exact fp32 for near-tie tokens ----
    __syncthreads();
    int nresc = min(s_cnt2, 64);
    for (int r = 0; r < nresc; r++) {
        int t  = s_list[r];
        int gt = tBlk + t;
        int e = tid & 63, seg = tid >> 6;
        const float* xr = x + (size_t)gt * H + seg * 256;
        const float* wr = w + (size_t)e  * H + seg * 256;
        float s = 0.0f;
#pragma unroll 4
        for (int k = 0; k < 256; k += 4) {
            float4 xv = *(const float4*)(xr + k);
            float4 wv = *(const float4*)(wr + k);
            s = fmaf(xv.x, wv.x, s); s = fmaf(xv.y, wv.y, s);
            s = fmaf(xv.z, wv.z, s); s = fmaf(xv.w, wv.w, s);
        }
        s_part[seg][e] = s;
        __syncthreads();
        if (wid == 0) {
            float v0 = s_part[0][lid] + s_part[1][lid] + s_part[2][lid] + s_part[3][lid];
            int   l1 = lid + 32;
            float v1 = s_part[0][l1] + s_part[1][l1] + s_part[2][l1] + s_part[3][l1];
            float b1, b2; int i1, i2;
            if (CMPGT(v0, lid, v1, l1)) { b1 = v0; i1 = lid; b2 = v1; i2 = l1; }
            else                        { b1 = v1; i1 = l1;  b2 = v0; i2 = lid; }
#pragma unroll
            for (int off = 16; off > 0; off >>= 1) {
                float c1 = __shfl_down_sync(0xffffffffu, b1, off);
                int  ci1 = __shfl_down_sync(0xffffffffu, i1, off);
                float c2 = __shfl_down_sync(0xffffffffu, b2, off);
                int  ci2 = __shfl_down_sync(0xffffffffu, i2, off);
                if (lid + off < 32) {
                    if (CMPGT(c1, ci1, b1, i1)) {
                        if (CMPGT(b1, i1, c2, ci2)) { b2 = b1; i2 = i1; }
                        else                        { b2 = c2; i2 = ci2; }
                        b1 = c1; i1 = ci1;
                    } else if (CMPGT(c1, ci1, b2, i2)) { b2 = c1; i2 = ci1; }
                }
            }
            float m  = __shfl_sync(0xffffffffu, b1, 0);
            float ex = __expf(v0 - m) + __expf(v1 - m);
#pragma unroll
            for (int off = 16; off > 0; off >>= 1)
                ex += __shfl_down_sync(0xffffffffu, ex, off);
            if (lid == 0) {
                float inv = 1.0f / ex;
                float p1 = __expf(b1 - m) * inv;
                float p2 = __expf(b2 - m) * inv;
                float dd = __expf(p2 - p1);
                out[2 * gt]             = 1.0f / (1.0f + dd);
                out[2 * gt + 1]         = dd / (1.0f + dd);
                out[2 * T + 2 * gt]     = (float)i1;
                out[2 * T + 2 * gt + 1] = (float)i2;
            }
        }
        __syncthreads();
    }

    // ---- fused finalize: last block computes the loss ----
    __threadfence();
    __syncthreads();
    if (tid == 0)
        s_last = (atomicAdd(&g_cnt, 1u) == (unsigned)(gridDim.x - 1)) ? 1u : 0u;
    __syncthreads();
    if (s_last) {
        __threadfence();
        float* redA = (float*)dsm;       // [4][64]
        float* redZ = redA + 256;        // [256]
        int e = tid & 63, part = tid >> 6;
        float s = 0.0f;
#pragma unroll 4
        for (int b = part; b < NBLK; b += 4) s += g_pexp[b * NE + e];
        float z2 = (tid < NBLK) ? g_pz2[tid] : 0.0f;
        __syncthreads();
        redA[part * 64 + e] = s;
        redZ[tid] = z2;
        __syncthreads();
        if (tid < 64) {
            float load = (redA[tid] + redA[64 + tid] + redA[128 + tid] + redA[192 + tid]) / (float)T;
            float dv = load - 1.0f / 64.0f;
            float lb = dv * dv;
            float zz = redZ[tid] + redZ[tid + 64] + redZ[tid + 128] + redZ[tid + 192];
#pragma unroll
            for (int off = 16; off > 0; off >>= 1) {
                lb += __shfl_down_sync(0xffffffffu, lb, off);
                zz += __shfl_down_sync(0xffffffffu, zz, off);
            }
            if (lid == 0) { s_red[wid] = lb; s_red[4 + wid] = zz; }
        }
        __syncthreads();
        if (tid == 0) {
            out[4 * T] = 0.01f * 64.0f * (s_red[0] + s_red[1])
                       + 1e-4f * ((s_red[4] + s_red[5]) / (float)T);
            g_cnt = 0;
        }
    }
}

extern "C" void kernel_launch(void* const* d_in, const int* in_sizes, int n_in,
                              void* d_out, int out_size) {
    const float* x = (const float*)d_in[0];
    const float* w = (const float*)d_in[1];
    float* out = (float*)d_out;
    int T = in_sizes[0] / H;   // 16384
    cudaFuncSetAttribute(moe_gate, cudaFuncAttributeMaxDynamicSharedMemorySize, DSMEM);
    moe_gate<<<T / TM, NT, DSMEM>>>(x, w, out, T);
}

// round 7
// speedup vs baseline: 1.5060x; 1.5060x over previous
#include <cuda_runtime.h>
#include <cstdint>

// MoE gating, exact fp32 via FFMA2 (f32x2). x:[16384,1024], gate_w:[64,1024].
// out (f32): top_scores [T,2] | top_idx [T,2] | total_loss [1].

#define H      1024
#define NE     64
#define TM     64
#define NT     256
#define KC     16
#define NCHUNK 64
#define XSTR   132                 // dup-x row stride (floats)
#define WSTR   72                  // w row stride (floats)
#define XB     (KC * XSTR)         // 2112
#define WB     (KC * WSTR)         // 1152
#define BUF    (XB + WB)           // 3264 floats per stage
#define SP_STR 66
#define NBLK   256

__device__ float    g_pexp[NBLK * NE];
__device__ float    g_pz2[NBLK];
__device__ unsigned g_cnt = 0;

typedef unsigned long long ull;

__device__ __forceinline__ void fma_f32x2(ull& d, ull a, ull b) {
    asm("fma.rn.f32x2 %0, %1, %2, %0;" : "+l"(d) : "l"(a), "l"(b));
}

__global__ __launch_bounds__(NT) void moe_gate(const float* __restrict__ x,
                                               const float* __restrict__ w,
                                               float* __restrict__ out,
                                               int T) {
    __shared__ __align__(16) float smem[2 * BUF];   // 26112 B
    __shared__ float    s_red[8];
    __shared__ unsigned s_last;

    const int tid  = threadIdx.x;
    const int wid  = tid >> 5;
    const int lid  = tid & 31;
    const int tBlk = blockIdx.x * TM;

    // compute map: 2 tokens x 8 experts per thread (expert-pair f32x2 accs)
    const int tx = tid & 7;          // e0 = 8*tx
    const int ty = tid >> 3;         // t0 = 2*ty  (0..62)
    const int e0 = tx * 8;
    const int t0 = ty * 2;

    ull acc[2][4];
#pragma unroll
    for (int i = 0; i < 2; i++)
#pragma unroll
        for (int j = 0; j < 4; j++) acc[i][j] = 0ull;

    // staging map: one float4 of x and one of w per thread per chunk
    const int xTok = tid >> 2;            // 0..63
    const int xK   = (tid & 3) * 4;       // 0,4,8,12
    const float* xg = x + (size_t)(tBlk + xTok) * H + xK;
    const float* wg = w + (size_t)xTok * H + xK;   // wE == xTok (64 experts)

    float4 xv = *(const float4*)(xg);
    float4 wv = *(const float4*)(wg);

    // store chunk 0 -> stage 0
    {
        float* xs = smem;
        float* ws = smem + XB;
        *(float2*)&xs[(xK + 0) * XSTR + 2 * xTok] = make_float2(xv.x, xv.x);
        *(float2*)&xs[(xK + 1) * XSTR + 2 * xTok] = make_float2(xv.y, xv.y);
        *(float2*)&xs[(xK + 2) * XSTR + 2 * xTok] = make_float2(xv.z, xv.z);
        *(float2*)&xs[(xK + 3) * XSTR + 2 * xTok] = make_float2(xv.w, xv.w);
        ws[(xK + 0) * WSTR + xTok] = wv.x;
        ws[(xK + 1) * WSTR + xTok] = wv.y;
        ws[(xK + 2) * WSTR + xTok] = wv.z;
        ws[(xK + 3) * WSTR + xTok] = wv.w;
    }

#pragma unroll 1
    for (int c = 0; c < NCHUNK; c++) {
        __syncthreads();
        if (c < NCHUNK - 1) {
            xv = *(const float4*)(xg + (c + 1) * KC);
            wv = *(const float4*)(wg + (c + 1) * KC);
        }
        const float* xs = smem + (c & 1) * BUF;
        const float* ws = xs + XB;
#pragma unroll
        for (int k = 0; k < KC; k++) {
            // a: (x_t,x_t),(x_t1,x_t1) — one LDS.128 (16B aligned, broadcast)
            ulonglong2 A = *(const ulonglong2*)(xs + k * XSTR + 2 * t0);
            // b: experts e0..e0+7 as 4 packed pairs — two LDS.128
            ulonglong2 B0 = *(const ulonglong2*)(ws + k * WSTR + e0);
            ulonglong2 B1 = *(const ulonglong2*)(ws + k * WSTR + e0 + 4);
            fma_f32x2(acc[0][0], A.x, B0.x);
            fma_f32x2(acc[0][1], A.x, B0.y);
            fma_f32x2(acc[0][2], A.x, B1.x);
            fma_f32x2(acc[0][3], A.x, B1.y);
            fma_f32x2(acc[1][0], A.y, B0.x);
            fma_f32x2(acc[1][1], A.y, B0.y);
            fma_f32x2(acc[1][2], A.y, B1.x);
            fma_f32x2(acc[1][3], A.y, B1.y);
        }
        if (c < NCHUNK - 1) {
            float* xs2 = smem + ((c + 1) & 1) * BUF;
            float* ws2 = xs2 + XB;
            *(float2*)&xs2[(xK + 0) * XSTR + 2 * xTok] = make_float2(xv.x, xv.x);
            *(float2*)&xs2[(xK + 1) * XSTR + 2 * xTok] = make_float2(xv.y, xv.y);
            *(float2*)&xs2[(xK + 2) * XSTR + 2 * xTok] = make_float2(xv.z, xv.z);
            *(float2*)&xs2[(xK + 3) * XSTR + 2 * xTok] = make_float2(xv.w, xv.w);
            ws2[(xK + 0) * WSTR + xTok] = wv.x;
            ws2[(xK + 1) * WSTR + xTok] = wv.y;
            ws2[(xK + 2) * WSTR + xTok] = wv.z;
            ws2[(xK + 3) * WSTR + xTok] = wv.w;
        }
    }
    __syncthreads();

    // ---- logits -> smem [TM][SP_STR] ----
    float* sP   = smem;               // 64*66 = 4224
    float* sInv = sP + TM * SP_STR;   // 64
#pragma unroll
    for (int i = 0; i < 2; i++)
#pragma unroll
        for (int j = 0; j < 4; j++) {
            float2 f = *(float2*)&acc[i][j];
            *(float2*)&sP[(t0 + i) * SP_STR + e0 + 2 * j] = f;
        }
    __syncthreads();

    // ---- per-token softmax / top-2 ----
    float zsq = 0.0f;
    if (tid < TM) {
        float* row = sP + tid * SP_STR;
        float b1 = -1e30f, b2 = -1e30f;
        int   i1 = 0, i2 = 0;
#pragma unroll 8
        for (int e = 0; e < NE; e++) {
            float l = row[e];
            if (l > b1)      { b2 = b1; i2 = i1; b1 = l; i1 = e; }
            else if (l > b2) { b2 = l;  i2 = e; }
        }
        float m = b1, sum = 0.0f;
#pragma unroll 8
        for (int e = 0; e < NE; e++) {
            float ex = __expf(row[e] - m);
            sum += ex;
            row[e] = ex;
        }
        float inv = 1.0f / sum;
        sInv[tid] = inv;
        float z = m + __logf(sum);
        zsq = z * z;
        float p1 = __expf(b1 - m) * inv;
        float p2 = __expf(b2 - m) * inv;
        float dd = __expf(p2 - p1);
        int gt = tBlk + tid;
        out[2 * gt]             = 1.0f / (1.0f + dd);
        out[2 * gt + 1]         = dd / (1.0f + dd);
        out[2 * T + 2 * gt]     = (float)i1;
        out[2 * T + 2 * gt + 1] = (float)i2;
    }

    // ---- loss partials ----
#pragma unroll
    for (int off = 16; off > 0; off >>= 1)
        zsq += __shfl_down_sync(0xffffffffu, zsq, off);
    if (lid == 0) s_red[wid] = zsq;
    __syncthreads();
    if (tid == 0) {
        float s = 0.0f;
#pragma unroll
        for (int i = 0; i < 8; i++) s += s_red[i];
        g_pz2[blockIdx.x] = s;
    }
    if (tid < NE) {
        float s = 0.0f;
#pragma unroll 4
        for (int t = 0; t < TM; t++) s += sP[t * SP_STR + tid] * sInv[t];
        g_pexp[blockIdx.x * NE + tid] = s;
    }

    // ---- fused finalize: last block computes the loss ----
    __threadfence();
    __syncthreads();
    if (tid == 0)
        s_last = (atomicAdd(&g_cnt, 1u) == (unsigned)(gridDim.x - 1)) ? 1u : 0u;
    __syncthreads();
    if (s_last) {
        __threadfence();
        float* redA = smem;          // [4][64]
        float* redZ = smem + 256;    // [256]
        int e = tid & 63, part = tid >> 6;
        float s = 0.0f;
#pragma unroll 4
        for (int b = part; b < NBLK; b += 4) s += g_pexp[b * NE + e];
        float z2 = g_pz2[tid];
        __syncthreads();
        redA[part * 64 + e] = s;
        redZ[tid] = z2;
        __syncthreads();
        if (tid < 64) {
            float load = (redA[tid] + redA[64 + tid] + redA[128 + tid] + redA[192 + tid]) / (float)T;
            float dv = load - 1.0f / 64.0f;
            float lb = dv * dv;
            float zz = redZ[tid] + redZ[tid + 64] + redZ[tid + 128] + redZ[tid + 192];
#pragma unroll
            for (int off = 16; off > 0; off >>= 1) {
                lb += __shfl_down_sync(0xffffffffu, lb, off);
                zz += __shfl_down_sync(0xffffffffu, zz, off);
            }
            if (lid == 0) { s_red[wid] = lb; s_red[4 + wid] = zz; }
        }
        __syncthreads();
        if (tid == 0) {
            out[4 * T] = 0.01f * 64.0f * (s_red[0] + s_red[1])
                       + 1e-4f * ((s_red[4] + s_red[5]) / (float)T);
            g_cnt = 0;
        }
    }
}

extern "C" void kernel_launch(void* const* d_in, const int* in_sizes, int n_in,
                              void* d_out, int out_size) {
    const float* x = (const float*)d_in[0];
    const float* w = (const float*)d_in[1];
    float* out = (float*)d_out;
    int T = in_sizes[0] / H;   // 16384
    moe_gate<<<T / TM, NT>>>(x, w, out, T);   // grid = 256
}

// round 8
// speedup vs baseline: 3.1030x; 2.0603x over previous
#include <cuda_runtime.h>
#include <cstdint>

// MoE gating, exact fp32, crossbar-balanced FFMA2 GEMM.
// x:[16384,1024] f32, gate_w:[64,1024] f32.
// out (f32): top_scores [T,2] | top_idx [T,2] | total_loss [1].

#define H      1024
#define NE     64
#define TM     64
#define NT     128
#define KC     16
#define NCH    64
#define XSTR   130                 // dup-x row stride (floats), even
#define WSTR   66                  // w row stride (floats), even
#define XB     (KC * XSTR)         // 2080
#define WB     (KC * WSTR)         // 1056
#define BUF    (XB + WB)           // 3136 floats / stage
#define SP_STR 66
#define NBLK   256

__device__ float    g_pexp[NBLK * NE];
__device__ float    g_pz2[NBLK];
__device__ unsigned g_cnt = 0;

typedef unsigned long long ull;

__device__ __forceinline__ void fma_f32x2(ull& d, ull a, ull b) {
    asm("fma.rn.f32x2 %0, %1, %2, %0;" : "+l"(d) : "l"(a), "l"(b));
}

__global__ __launch_bounds__(NT) void moe_gate(const float* __restrict__ x,
                                               const float* __restrict__ w,
                                               float* __restrict__ out,
                                               int T) {
    __shared__ __align__(16) float smem[2 * BUF];   // 25088 B
    __shared__ float    s_red[8];
    __shared__ unsigned s_last;

    const int tid  = threadIdx.x;
    const int wid  = tid >> 5;
    const int lid  = tid & 31;
    const int tBlk = blockIdx.x * TM;

    // compute map: tokens {ty+16i}, expert pairs {2tx+16j, +1}
    const int tx = tid & 7;
    const int ty = tid >> 3;

    ull acc[4][4];
#pragma unroll
    for (int i = 0; i < 4; i++)
#pragma unroll
        for (int j = 0; j < 4; j++) acc[i][j] = 0ull;

    // staging maps
    const int sTok = tid >> 2;            // 0..31 (and +32)
    const int kq   = (tid & 3) * 4;       // 0,4,8,12
    const float* xg0 = x + (size_t)(tBlk + sTok) * H + kq;
    const float* xg1 = xg0 + (size_t)32 * H;
    const int wE  = tid >> 1;             // 0..63
    const int wkq = (tid & 1) * 8;        // 0 or 8
    const float* wg = w + (size_t)wE * H + wkq;

    float4 xa = *(const float4*)(xg0);
    float4 xb = *(const float4*)(xg1);
    float4 wa = *(const float4*)(wg);
    float4 wb = *(const float4*)(wg + 4);

    // store chunk 0 -> stage 0
    {
        float* xs = smem;
        float* ws = smem + XB;
        *(float2*)&xs[(kq + 0) * XSTR + 2 * sTok] = make_float2(xa.x, xa.x);
        *(float2*)&xs[(kq + 1) * XSTR + 2 * sTok] = make_float2(xa.y, xa.y);
        *(float2*)&xs[(kq + 2) * XSTR + 2 * sTok] = make_float2(xa.z, xa.z);
        *(float2*)&xs[(kq + 3) * XSTR + 2 * sTok] = make_float2(xa.w, xa.w);
        *(float2*)&xs[(kq + 0) * XSTR + 2 * (sTok + 32)] = make_float2(xb.x, xb.x);
        *(float2*)&xs[(kq + 1) * XSTR + 2 * (sTok + 32)] = make_float2(xb.y, xb.y);
        *(float2*)&xs[(kq + 2) * XSTR + 2 * (sTok + 32)] = make_float2(xb.z, xb.z);
        *(float2*)&xs[(kq + 3) * XSTR + 2 * (sTok + 32)] = make_float2(xb.w, xb.w);
        ws[(wkq + 0) * WSTR + wE] = wa.x;
        ws[(wkq + 1) * WSTR + wE] = wa.y;
        ws[(wkq + 2) * WSTR + wE] = wa.z;
        ws[(wkq + 3) * WSTR + wE] = wa.w;
        ws[(wkq + 4) * WSTR + wE] = wb.x;
        ws[(wkq + 5) * WSTR + wE] = wb.y;
        ws[(wkq + 6) * WSTR + wE] = wb.z;
        ws[(wkq + 7) * WSTR + wE] = wb.w;
    }

#pragma unroll 1
    for (int c = 0; c < NCH; c++) {
        __syncthreads();
        if (c < NCH - 1) {
            xa = *(const float4*)(xg0 + (c + 1) * KC);
            xb = *(const float4*)(xg1 + (c + 1) * KC);
            wa = *(const float4*)(wg + (c + 1) * KC);
            wb = *(const float4*)(wg + (c + 1) * KC + 4);
        }
        const float* xs = smem + (c & 1) * BUF;
        const float* ws = xs + XB;
#pragma unroll
        for (int k = 0; k < KC; k++) {
            ull a[4], b[4];
#pragma unroll
            for (int i = 0; i < 4; i++)
                a[i] = *(const ull*)(xs + k * XSTR + 2 * ty + 32 * i);
#pragma unroll
            for (int j = 0; j < 4; j++)
                b[j] = *(const ull*)(ws + k * WSTR + 2 * tx + 16 * j);
#pragma unroll
            for (int i = 0; i < 4; i++)
#pragma unroll
                for (int j = 0; j < 4; j++)
                    fma_f32x2(acc[i][j], a[i], b[j]);
        }
        if (c < NCH - 1) {
            float* xs2 = smem + ((c + 1) & 1) * BUF;
            float* ws2 = xs2 + XB;
            *(float2*)&xs2[(kq + 0) * XSTR + 2 * sTok] = make_float2(xa.x, xa.x);
            *(float2*)&xs2[(kq + 1) * XSTR + 2 * sTok] = make_float2(xa.y, xa.y);
            *(float2*)&xs2[(kq + 2) * XSTR + 2 * sTok] = make_float2(xa.z, xa.z);
            *(float2*)&xs2[(kq + 3) * XSTR + 2 * sTok] = make_float2(xa.w, xa.w);
            *(float2*)&xs2[(kq + 0) * XSTR + 2 * (sTok + 32)] = make_float2(xb.x, xb.x);
            *(float2*)&xs2[(kq + 1) * XSTR + 2 * (sTok + 32)] = make_float2(xb.y, xb.y);
            *(float2*)&xs2[(kq + 2) * XSTR + 2 * (sTok + 32)] = make_float2(xb.z, xb.z);
            *(float2*)&xs2[(kq + 3) * XSTR + 2 * (sTok + 32)] = make_float2(xb.w, xb.w);
            ws2[(wkq + 0) * WSTR + wE] = wa.x;
            ws2[(wkq + 1) * WSTR + wE] = wa.y;
            ws2[(wkq + 2) * WSTR + wE] = wa.z;
            ws2[(wkq + 3) * WSTR + wE] = wa.w;
            ws2[(wkq + 4) * WSTR + wE] = wb.x;
            ws2[(wkq + 5) * WSTR + wE] = wb.y;
            ws2[(wkq + 6) * WSTR + wE] = wb.z;
            ws2[(wkq + 7) * WSTR + wE] = wb.w;
        }
    }
    __syncthreads();

    // ---- logits -> smem [TM][SP_STR] ----
    float* sP   = smem;               // 64*66 = 4224
    float* sInv = sP + TM * SP_STR;   // 64
#pragma unroll
    for (int i = 0; i < 4; i++)
#pragma unroll
        for (int j = 0; j < 4; j++) {
            float2 f = *(float2*)&acc[i][j];
            *(float2*)&sP[(ty + 16 * i) * SP_STR + 2 * tx + 16 * j] = f;
        }
    __syncthreads();

    // ---- per-token softmax / top-2 ----
    float zsq = 0.0f;
    if (tid < TM) {
        float* row = sP + tid * SP_STR;
        float b1 = -1e30f, b2 = -1e30f;
        int   i1 = 0, i2 = 0;
#pragma unroll 8
        for (int e = 0; e < NE; e++) {
            float l = row[e];
            if (l > b1)      { b2 = b1; i2 = i1; b1 = l; i1 = e; }
            else if (l > b2) { b2 = l;  i2 = e; }
        }
        float m = b1, sum = 0.0f;
#pragma unroll 8
        for (int e = 0; e < NE; e++) {
            float ex = __expf(row[e] - m);
            sum += ex;
            row[e] = ex;
        }
        float inv = 1.0f / sum;
        sInv[tid] = inv;
        float z = m + __logf(sum);
        zsq = z * z;
        float p1 = __expf(b1 - m) * inv;
        float p2 = __expf(b2 - m) * inv;
        float dd = __expf(p2 - p1);
        int gt = tBlk + tid;
        out[2 * gt]             = 1.0f / (1.0f + dd);
        out[2 * gt + 1]         = dd / (1.0f + dd);
        out[2 * T + 2 * gt]     = (float)i1;
        out[2 * T + 2 * gt + 1] = (float)i2;
    }

    // ---- loss partials ----
#pragma unroll
    for (int off = 16; off > 0; off >>= 1)
        zsq += __shfl_down_sync(0xffffffffu, zsq, off);
    if (lid == 0) s_red[wid] = zsq;
    __syncthreads();
    if (tid == 0)
        g_pz2[blockIdx.x] = s_red[0] + s_red[1] + s_red[2] + s_red[3];
    if (tid < NE) {
        float s = 0.0f;
#pragma unroll 4
        for (int t = 0; t < TM; t++) s += sP[t * SP_STR + tid] * sInv[t];
        g_pexp[blockIdx.x * NE + tid] = s;
    }

    // ---- fused finalize: last block computes the loss ----
    __threadfence();
    __syncthreads();
    if (tid == 0)
        s_last = (atomicAdd(&g_cnt, 1u) == (unsigned)(gridDim.x - 1)) ? 1u : 0u;
    __syncthreads();
    if (s_last) {
        __threadfence();
        int e = tid & 63, part = tid >> 6;        // part: 0..1
        float s = 0.0f;
#pragma unroll 4
        for (int b = part; b < NBLK; b += 2) s += g_pexp[b * NE + e];
        float z2 = g_pz2[tid] + g_pz2[tid + 128];
        __syncthreads();
        float* redA = smem;          // [2][64]
        float* redZ = smem + 128;    // [128]
        redA[part * 64 + e] = s;
        redZ[tid] = z2;
        __syncthreads();
        if (tid < 64) {
            float load = (redA[tid] + redA[64 + tid]) / (float)T;
            float dv = load - 1.0f / 64.0f;
            float lb = dv * dv;
            float zz = redZ[tid] + redZ[tid + 64];
#pragma unroll
            for (int off = 16; off > 0; off >>= 1) {
                lb += __shfl_down_sync(0xffffffffu, lb, off);
                zz += __shfl_down_sync(0xffffffffu, zz, off);
            }
            if (lid == 0) { s_red[wid] = lb; s_red[4 + wid] = zz; }
        }
        __syncthreads();
        if (tid == 0) {
            out[4 * T] = 0.01f * 64.0f * (s_red[0] + s_red[1])
                       + 1e-4f * ((s_red[4] + s_red[5]) / (float)T);
            g_cnt = 0;
        }
    }
}

extern "C" void kernel_launch(void* const* d_in, const int* in_sizes, int n_in,
                              void* d_out, int out_size) {
    const float* x = (const float*)d_in[0];
    const float* w = (const float*)d_in[1];
    float* out = (float*)d_out;
    int T = in_sizes[0] / H;   // 16384
    moe_gate<<<T / TM, NT>>>(x, w, out, T);   // grid = 256
}

// round 9
// speedup vs baseline: 4.0648x; 1.3100x over previous
#include <cuda_runtime.h>
#include <cstdint>

// MoE gating, exact fp32, K-packed f32x2 GEMM (no dup, no transpose).
// x:[16384,1024] f32, gate_w:[64,1024] f32.
// out (f32): top_scores [T,2] | top_idx [T,2] | total_loss [1].

#define H      1024
#define NE     64
#define TM     128
#define NT     256
#define KC     32
#define NSTEP  16                  // 512 k per half / KC
#define RS     36                  // smem row stride (floats)
#define XLo    0
#define XHi    (128 * RS)          // 4608
#define WLo    (256 * RS)          // 9216
#define WHi    (WLo + 64 * RS)     // 11520
#define STG    (WHi + 64 * RS)     // 13824 floats / stage
#define DSMEM  (2 * STG * 4)       // 110592 B
#define SPS    65
#define NBLK   128

__device__ float    g_pexp[NBLK * NE];
__device__ float    g_pz2[NBLK];
__device__ unsigned g_cnt = 0;

typedef unsigned long long ull;

__device__ __forceinline__ void fma2(ull& d, ull a, ull b) {
    asm("fma.rn.f32x2 %0, %1, %2, %0;" : "+l"(d) : "l"(a), "l"(b));
}
__device__ __forceinline__ uint32_t su32(const void* p) {
    uint32_t a;
    asm("{ .reg .u64 t; cvta.to.shared.u64 t, %1; cvt.u32.u64 %0, t; }"
        : "=r"(a) : "l"(p));
    return a;
}
__device__ __forceinline__ void cpa16(uint32_t dst, const float* src) {
    asm volatile("cp.async.cg.shared.global [%0], [%1], 16;" :: "r"(dst), "l"(src));
}

__global__ void __launch_bounds__(NT, 1) moe_gate(const float* __restrict__ x,
                                                  const float* __restrict__ w,
                                                  float* __restrict__ out,
                                                  int T) {
    extern __shared__ __align__(16) float dsm[];
    __shared__ float    s_red[8];
    __shared__ unsigned s_last;

    const int tid  = threadIdx.x;
    const int wid  = tid >> 5;
    const int lid  = tid & 31;
    const int tBlk = blockIdx.x * TM;
    const uint32_t sb = su32(dsm);

    // compute map
    const int khalf = wid >> 2;            // 0: k<512, 1: k>=512
    const int wq    = wid & 3;
    const int tx    = lid & 7;             // experts {tx+8j}
    const int ty    = lid >> 3;
    const int g     = wq * 4 + ty;         // tokens {g+16i}

    ull acc[8][8];
#pragma unroll
    for (int i = 0; i < 8; i++)
#pragma unroll
        for (int j = 0; j < 8; j++) acc[i][j] = 0ull;

    // staging map (all 256 threads stage all 4 regions)
    const int st = tid >> 3;               // row helper
    const int sq = tid & 7;                // 16B quad within 32-float row

    // ---- stage(s, slot) as a lambda-less macro body ----
#define STAGE(s_, slot_) do {                                                    \
    int _k0 = (s_) * KC;                                                         \
    uint32_t _sbase = sb + (slot_) * (STG * 4);                                  \
    _Pragma("unroll")                                                            \
    for (int r = 0; r < 4; r++) {                                                \
        int t_ = (r * 256 + tid) >> 3;                                           \
        const float* srcL = x + (size_t)(tBlk + t_) * H + _k0 + sq * 4;          \
        cpa16(_sbase + (XLo + t_ * RS + sq * 4) * 4, srcL);                      \
        cpa16(_sbase + (XHi + t_ * RS + sq * 4) * 4, srcL + 512);                \
    }                                                                            \
    _Pragma("unroll")                                                            \
    for (int r = 0; r < 2; r++) {                                                \
        int e_ = (r * 256 + tid) >> 3;                                           \
        const float* srcW = w + (size_t)e_ * H + _k0 + sq * 4;                   \
        cpa16(_sbase + (WLo + e_ * RS + sq * 4) * 4, srcW);                      \
        cpa16(_sbase + (WHi + e_ * RS + sq * 4) * 4, srcW + 512);                \
    }                                                                            \
} while (0)

    // prologue
    STAGE(0, 0);
    asm volatile("cp.async.commit_group;" ::: "memory");

#pragma unroll 1
    for (int s = 0; s < NSTEP; s++) {
        asm volatile("cp.async.wait_group 0;" ::: "memory");
        __syncthreads();
        if (s + 1 < NSTEP) STAGE(s + 1, (s + 1) & 1);
        asm volatile("cp.async.commit_group;" ::: "memory");

        const float* xs = dsm + (s & 1) * STG + (khalf ? XHi : XLo) + g * RS;
        const float* ws = dsm + (s & 1) * STG + (khalf ? WHi : WLo) + tx * RS;
#pragma unroll 4
        for (int kh = 0; kh < 16; kh++) {
            ull a[8], b[8];
#pragma unroll
            for (int i = 0; i < 8; i++)
                a[i] = *(const ull*)(xs + i * 16 * RS + 2 * kh);
#pragma unroll
            for (int j = 0; j < 8; j++)
                b[j] = *(const ull*)(ws + j * 8 * RS + 2 * kh);
#pragma unroll
            for (int i = 0; i < 8; i++)
#pragma unroll
                for (int j = 0; j < 8; j++)
                    fma2(acc[i][j], a[i], b[j]);
        }
    }
    __syncthreads();

    // ---- merge k-halves: logits -> sP[128][SPS] ----
    float* sP   = dsm;                 // 128*65 = 8320 floats (slot-0 area, free)
    float* sInv = dsm + 128 * SPS;     // 128
    if (khalf == 0) {
#pragma unroll
        for (int i = 0; i < 8; i++)
#pragma unroll
            for (int j = 0; j < 8; j++) {
                float2 f = *(float2*)&acc[i][j];
                sP[(g + 16 * i) * SPS + tx + 8 * j] = f.x + f.y;
            }
    }
    __syncthreads();
    if (khalf == 1) {
#pragma unroll
        for (int i = 0; i < 8; i++)
#pragma unroll
            for (int j = 0; j < 8; j++) {
                float2 f = *(float2*)&acc[i][j];
                sP[(g + 16 * i) * SPS + tx + 8 * j] += f.x + f.y;
            }
    }
    __syncthreads();

    // ---- per-token softmax / top-2 ----
    float zsq = 0.0f;
    if (tid < TM) {
        float* row = sP + tid * SPS;
        float b1 = -1e30f, b2 = -1e30f;
        int   i1 = 0, i2 = 0;
#pragma unroll 8
        for (int e = 0; e < NE; e++) {
            float l = row[e];
            if (l > b1)      { b2 = b1; i2 = i1; b1 = l; i1 = e; }
            else if (l > b2) { b2 = l;  i2 = e; }
        }
        float m = b1, sum = 0.0f;
#pragma unroll 8
        for (int e = 0; e < NE; e++) {
            float ex = __expf(row[e] - m);
            sum += ex;
            row[e] = ex;
        }
        float inv = 1.0f / sum;
        sInv[tid] = inv;
        float z = m + __logf(sum);
        zsq = z * z;
        float p1 = __expf(b1 - m) * inv;
        float p2 = __expf(b2 - m) * inv;
        float dd = __expf(p2 - p1);
        int gt = tBlk + tid;
        out[2 * gt]             = 1.0f / (1.0f + dd);
        out[2 * gt + 1]         = dd / (1.0f + dd);
        out[2 * T + 2 * gt]     = (float)i1;
        out[2 * T + 2 * gt + 1] = (float)i2;
    }

    // ---- loss partials ----
#pragma unroll
    for (int off = 16; off > 0; off >>= 1)
        zsq += __shfl_down_sync(0xffffffffu, zsq, off);
    if (lid == 0) s_red[wid] = zsq;
    __syncthreads();
    if (tid == 0) {
        float s = 0.0f;
#pragma unroll
        for (int i = 0; i < 8; i++) s += s_red[i];
        g_pz2[blockIdx.x] = s;
    }
    if (tid < NE) {
        float s = 0.0f;
#pragma unroll 4
        for (int t = 0; t < TM; t++) s += sP[t * SPS + tid] * sInv[t];
        g_pexp[blockIdx.x * NE + tid] = s;
    }

    // ---- fused finalize: last block computes the loss ----
    __threadfence();
    __syncthreads();
    if (tid == 0)
        s_last = (atomicAdd(&g_cnt, 1u) == (unsigned)(gridDim.x - 1)) ? 1u : 0u;
    __syncthreads();
    if (s_last) {
        __threadfence();
        int e = tid & 63, part = tid >> 6;           // part 0..3
        float s = 0.0f;
#pragma unroll 4
        for (int b = part; b < NBLK; b += 4) s += g_pexp[b * NE + e];
        float z2 = (tid < NBLK) ? g_pz2[tid] : 0.0f;
        __syncthreads();
        float* redA = dsm;           // [4][64]
        float* redZ = dsm + 256;     // [256]
        redA[part * 64 + e] = s;
        redZ[tid] = z2;
        __syncthreads();
        if (tid < 64) {
            float load = (redA[tid] + redA[64 + tid] + redA[128 + tid] + redA[192 + tid]) / (float)T;
            float dv = load - 1.0f / 64.0f;
            float lb = dv * dv;
            float zz = redZ[tid] + redZ[tid + 64] + redZ[tid + 128] + redZ[tid + 192];
#pragma unroll
            for (int off = 16; off > 0; off >>= 1) {
                lb += __shfl_down_sync(0xffffffffu, lb, off);
                zz += __shfl_down_sync(0xffffffffu, zz, off);
            }
            if (lid == 0) { s_red[wid] = lb; s_red[4 + wid] = zz; }
        }
        __syncthreads();
        if (tid == 0) {
            out[4 * T] = 0.01f * 64.0f * (s_red[0] + s_red[1])
                       + 1e-4f * ((s_red[4] + s_red[5]) / (float)T);
            g_cnt = 0;
        }
    }
}

extern "C" void kernel_launch(void* const* d_in, const int* in_sizes, int n_in,
                              void* d_out, int out_size) {
    const float* x = (const float*)d_in[0];
    const float* w = (const float*)d_in[1];
    float* out = (float*)d_out;
    int T = in_sizes[0] / H;   // 16384
    cudaFuncSetAttribute(moe_gate, cudaFuncAttributeMaxDynamicSharedMemorySize, DSMEM);
    moe_gate<<<T / TM, NT, DSMEM>>>(x, w, out, T);   // grid = 128
}